// round 15
// baseline (speedup 1.0000x reference)
#include <cuda_runtime.h>
#include <cuda_fp16.h>
#include <math.h>
#include <stdint.h>

// ---------------------------------------------------------------------------
// PredictorLG fused MLP:  LN -> (GEMM+GELU)x3 -> GEMM(->2) -> log_softmax
// R15: warp grid 4(m)x2(n) — m-groups of 16 rows, 2 warps each. A-ldsm
// redundancy halves (8->4 L1, ->2 L2); B bytes invariant. Four independent
// 64-thread pipelines per CTA (named barriers) for deeper phase overlap.
// Bias inline __ldg in epilogue to stay under 128 regs (no spills).
// ---------------------------------------------------------------------------

#define ROWS_TILE   64
#define NTHREADS    256
#define LD          392           // padded activation row stride (halfs)
#define RTOT        262144
#define ROWS_PER_M  131072

#define S1 (384*384)
#define S2 (384*192)
#define S3 (192*96)
#define MOD_STRIDE (S1+S2+S3)
#define OFF_L2 (S1)
#define OFF_L3 (S1+S2)

__device__ __align__(16) __half g_packedW[2 * MOD_STRIDE];

#define GROUP_BAR(g) \
    asm volatile("bar.sync %0, 64;" :: "r"(1 + (g)) : "memory")

// ---------------------------------------------------------------------------
// Weight repack: W[k][n] fp32 -> fp16 B-fragment layout, single-kt granules:
//   dst = base + ((nt*KT + kt)*32 + lane)*4 + reg*2 + i   (8B per lane per kt)
//   lane = (n%8)*4 + ((k%8)>>1);  reg = (k>>3)&1;  i = k&1
// ---------------------------------------------------------------------------
__global__ void pack_weights_kernel(const float* __restrict__ W1,
                                    const float* __restrict__ W2,
                                    const float* __restrict__ W3) {
    int idx = blockIdx.x * blockDim.x + threadIdx.x;
    const float* src;
    int K, N, r, m, layerOff;
    if (idx < 2 * S1) {
        m = idx / S1; r = idx % S1; K = 384; N = 384;
        src = W1 + m * S1; layerOff = 0;
    } else if (idx < 2 * (S1 + S2)) {
        int e = idx - 2 * S1;
        m = e / S2; r = e % S2; K = 384; N = 192;
        src = W2 + m * S2; layerOff = OFF_L2;
    } else if (idx < 2 * (S1 + S2 + S3)) {
        int e = idx - 2 * (S1 + S2);
        m = e / S3; r = e % S3; K = 192; N = 96;
        src = W3 + m * S3; layerOff = OFF_L3;
    } else {
        return;
    }
    int k = r / N, n = r % N;
    int kt  = k >> 4;
    int KT  = K >> 4;
    int nt  = n >> 3;
    int lane = (n & 7) * 4 + ((k & 7) >> 1);
    int reg  = (k >> 3) & 1;
    int i    = k & 1;
    int dst  = m * MOD_STRIDE + layerOff +
               ((nt * KT + kt) * 32 + lane) * 4 + reg * 2 + i;
    g_packedW[dst] = __float2half(src[k * N + n]);
}

// ---------------------------------------------------------------------------
// mma / ldmatrix / gelu helpers
// ---------------------------------------------------------------------------
__device__ __forceinline__ void mma16816(float c[4], const unsigned a[4],
                                         const unsigned b0, const unsigned b1) {
    asm volatile(
        "mma.sync.aligned.m16n8k16.row.col.f32.f16.f16.f32 "
        "{%0,%1,%2,%3}, {%4,%5,%6,%7}, {%8,%9}, {%0,%1,%2,%3};\n"
        : "+f"(c[0]), "+f"(c[1]), "+f"(c[2]), "+f"(c[3])
        : "r"(a[0]), "r"(a[1]), "r"(a[2]), "r"(a[3]), "r"(b0), "r"(b1));
}

__device__ __forceinline__ void ldmatrix_x4(unsigned r[4], uint32_t addr) {
    asm volatile(
        "ldmatrix.sync.aligned.m8n8.x4.shared.b16 {%0,%1,%2,%3}, [%4];\n"
        : "=r"(r[0]), "=r"(r[1]), "=r"(r[2]), "=r"(r[3])
        : "r"(addr));
}

// packed fp16 GELU (tanh approx, HW MUFU.TANH on f16x2)
__device__ __forceinline__ __half2 gelu_h2(__half2 v) {
    const __half2 c0 = __float2half2_rn(0.7978845608f);
    const __half2 c1 = __float2half2_rn(0.044715f);
    const __half2 hf = __float2half2_rn(0.5f);
    __half2 vv = __hmul2(v, v);
    __half2 u  = __hmul2(v, __hfma2(c1, vv, c0));
    unsigned ui = *(unsigned*)&u, ti;
    asm("tanh.approx.f16x2 %0, %1;" : "=r"(ti) : "r"(ui));
    __half2 t  = *(__half2*)&ti;
    __half2 hv = __hmul2(v, hf);
    return __hfma2(hv, t, hv);
}

// ---------------------------------------------------------------------------
// One GEMM layer (group-local): out = gelu(in[16rows,K] @ W[K,N] + bias).
// Warp grid 4(m) x 2(n): warp owns 16 rows x CW cols (CW = CHUNK/2).
// A: one ldmatrix.x4 per kt. B: single-kt uint2, 2-slot circular prefetch.
// Bias loaded inline in epilogue (register diet).
// ---------------------------------------------------------------------------
template <int K, int N, int CHUNK>
__device__ __forceinline__ void gemm_layer(const __half* inBuf,
                                           __half* outBuf,
                                           const __half* __restrict__ Wp,
                                           const float* __restrict__ bias) {
    constexpr int NPASS = N / CHUNK;
    constexpr int CW  = CHUNK / 2;
    constexpr int NF  = CW / 8;
    constexpr int KT  = K / 16;

    const int tid  = threadIdx.x;
    const int lane = tid & 31;
    const int wid  = tid >> 5;
    const int wm   = wid >> 1;       // m-group 0..3 (16 rows each)
    const int wn   = wid & 1;        // n-half

    uint32_t sA = (uint32_t)__cvta_generic_to_shared(inBuf);
    const int arow     = wm * 16 + (lane & 15);
    const int acol_off = (lane >> 4) * 8;
    const uint32_t aBase = sA + (uint32_t)((arow * LD + acol_off) * 2);

    const uint2* bb = (const uint2*)Wp;

#pragma unroll
    for (int p = 0; p < NPASS; ++p) {
        float acc[NF][4];
#pragma unroll
        for (int nf = 0; nf < NF; ++nf)
#pragma unroll
            for (int q = 0; q < 4; ++q) acc[nf][q] = 0.f;

        const int colbase = p * CHUNK + wn * CW;
        const int ntbase  = colbase >> 3;
        const uint2* bwarp = bb + (size_t)ntbase * KT * 32 + lane;
        const int cb = colbase + (lane & 3) * 2;

        // B: 2-slot circular single-kt prefetch (uint2 = 8B/lane)
        uint2 bf[2][NF];
#pragma unroll
        for (int nf = 0; nf < NF; ++nf)
            bf[0][nf] = __ldg(bwarp + (size_t)nf * KT * 32);

#pragma unroll
        for (int kt = 0; kt < KT; ++kt) {
            const int cur = kt & 1;
            if (kt + 1 < KT) {
#pragma unroll
                for (int nf = 0; nf < NF; ++nf)
                    bf[cur ^ 1][nf] =
                        __ldg(bwarp + (size_t)nf * KT * 32 + (kt + 1) * 32);
            }

            unsigned a[4];
            ldmatrix_x4(a, aBase + (uint32_t)(kt * 32));

#pragma unroll
            for (int nf = 0; nf < NF; ++nf)
                mma16816(acc[nf], a, bf[cur][nf].x, bf[cur][nf].y);
        }

        // epilogue: bias (inline ldg) + packed half2 gelu + store
        const int r0 = wm * 16 + (lane >> 2);
#pragma unroll
        for (int nf = 0; nf < NF; ++nf) {
            const int c = cb + nf * 8;
            const float b0 = __ldg(bias + c);
            const float b1 = __ldg(bias + c + 1);
            __half2 p01 = __floats2half2_rn(acc[nf][0] + b0, acc[nf][1] + b1);
            __half2 p23 = __floats2half2_rn(acc[nf][2] + b0, acc[nf][3] + b1);
            *(__half2*)(outBuf + r0 * LD + c)       = gelu_h2(p01);
            *(__half2*)(outBuf + (r0 + 8) * LD + c) = gelu_h2(p23);
        }
    }
}

// ---------------------------------------------------------------------------
// Fused kernel — four independent 64-thread pipelines per CTA.
// ---------------------------------------------------------------------------
__global__ void __launch_bounds__(NTHREADS, 2)
fused_mlp_kernel(const float* __restrict__ x,
                 const float* __restrict__ ln_g,
                 const float* __restrict__ ln_b,
                 const float* __restrict__ b1,
                 const float* __restrict__ b2,
                 const float* __restrict__ b3,
                 const float* __restrict__ W4,
                 const float* __restrict__ b4,
                 float* __restrict__ out) {
    extern __shared__ __align__(16) char smem_raw[];
    __half* bufA = (__half*)smem_raw;                               // [64][392]
    __half* bufB = bufA + ROWS_TILE * LD;                           // [64][392]

    const int tid  = threadIdx.x;
    const int lane = tid & 31;
    const int wid  = tid >> 5;
    const int wm   = wid >> 1;       // group 0..3
    const int wn   = wid & 1;
    const long row0 = (long)blockIdx.x * ROWS_TILE;
    const int m = (int)(row0 / ROWS_PER_M);

    // ------------------- Stage 0: LayerNorm -> bufA (fp16), group-local ----
    {
        float4 g4[3], bb4[3];
#pragma unroll
        for (int j = 0; j < 3; ++j) {
            g4[j]  = ((const float4*)(ln_g + m * 384))[j * 32 + lane];
            bb4[j] = ((const float4*)(ln_b + m * 384))[j * 32 + lane];
        }
        // group wm handles rows [wm*16, wm*16+16); warp wn takes 8 of them
#pragma unroll
        for (int t = 0; t < 8; ++t) {
            const int r = wm * 16 + wn * 8 + t;
            const float4* xr = (const float4*)(x + (row0 + r) * 384);
            float4 v[3];
            float s = 0.f, q = 0.f;
#pragma unroll
            for (int j = 0; j < 3; ++j) {
                v[j] = xr[j * 32 + lane];
                s += v[j].x + v[j].y + v[j].z + v[j].w;
                q += v[j].x * v[j].x + v[j].y * v[j].y +
                     v[j].z * v[j].z + v[j].w * v[j].w;
            }
#pragma unroll
            for (int off = 16; off; off >>= 1) {
                s += __shfl_xor_sync(0xffffffffu, s, off);
                q += __shfl_xor_sync(0xffffffffu, q, off);
            }
            const float mu   = s * (1.0f / 384.0f);
            const float var  = q * (1.0f / 384.0f) - mu * mu;
            const float rinv = rsqrtf(var + 1e-5f);
#pragma unroll
            for (int j = 0; j < 3; ++j) {
                const int c = (j * 32 + lane) * 4;
                float y0 = (v[j].x - mu) * rinv * g4[j].x + bb4[j].x;
                float y1 = (v[j].y - mu) * rinv * g4[j].y + bb4[j].y;
                float y2 = (v[j].z - mu) * rinv * g4[j].z + bb4[j].z;
                float y3 = (v[j].w - mu) * rinv * g4[j].w + bb4[j].w;
                *(__half2*)(bufA + r * LD + c)     = __floats2half2_rn(y0, y1);
                *(__half2*)(bufA + r * LD + c + 2) = __floats2half2_rn(y2, y3);
            }
        }
    }

    const __half* WpBase = g_packedW + (size_t)m * MOD_STRIDE;

    // ------------------- Layer 1: 384 -> 384 (2 passes of 192) -------------
    GROUP_BAR(wm);
    gemm_layer<384, 384, 192>(bufA, bufB, WpBase, b1 + m * 384);

    // ------------------- Layer 2: 384 -> 192 (1 pass of 192) ---------------
    GROUP_BAR(wm);
    gemm_layer<384, 192, 192>(bufB, bufA, WpBase + OFF_L2, b2 + m * 192);

    // ------------------- Layer 3: 192 -> 96 (1 pass of 96) -----------------
    GROUP_BAR(wm);
    gemm_layer<192, 96, 96>(bufA, bufB, WpBase + OFF_L3, b3 + m * 96);

    // ------------------- Layer 4: 96 -> 2 + log_softmax (group-local) ------
    GROUP_BAR(wm);
    {
        const int glt  = wn * 32 + lane;          // 0..63 within group
        const int r    = wm * 16 + (glt >> 2);    // 16 rows per group
        const int part = glt & 3;
        const float* w4 = W4 + m * 192;
        const __half* hrow = bufB + r * LD;
        float z0 = 0.f, z1 = 0.f;
#pragma unroll
        for (int kk = 0; kk < 12; ++kk) {
            const int k = part * 24 + kk * 2;
            __half2 hv = *(const __half2*)(hrow + k);
            float a0 = __half2float(hv.x);
            float a1 = __half2float(hv.y);
            z0 += a0 * __ldg(w4 + k * 2)       + a1 * __ldg(w4 + (k + 1) * 2);
            z1 += a0 * __ldg(w4 + k * 2 + 1)   + a1 * __ldg(w4 + (k + 1) * 2 + 1);
        }
        z0 += __shfl_xor_sync(0xffffffffu, z0, 1);
        z0 += __shfl_xor_sync(0xffffffffu, z0, 2);
        z1 += __shfl_xor_sync(0xffffffffu, z1, 1);
        z1 += __shfl_xor_sync(0xffffffffu, z1, 2);
        if (part == 0) {
            z0 += __ldg(b4 + m * 2 + 0);
            z1 += __ldg(b4 + m * 2 + 1);
            const float mx  = fmaxf(z0, z1);
            const float lse = mx + logf(expf(z0 - mx) + expf(z1 - mx));
            float* o = out + (row0 + r) * 2;
            o[0] = z0 - lse;
            o[1] = z1 - lse;
        }
    }
}

// ---------------------------------------------------------------------------
// Launch
// ---------------------------------------------------------------------------
extern "C" void kernel_launch(void* const* d_in, const int* in_sizes, int n_in,
                              void* d_out, int out_size) {
    const float* x    = (const float*)d_in[0];
    const float* ln_g = (const float*)d_in[1];
    const float* ln_b = (const float*)d_in[2];
    const float* W1   = (const float*)d_in[3];
    const float* b1   = (const float*)d_in[4];
    const float* W2   = (const float*)d_in[5];
    const float* b2   = (const float*)d_in[6];
    const float* W3   = (const float*)d_in[7];
    const float* b3   = (const float*)d_in[8];
    const float* W4   = (const float*)d_in[9];
    const float* b4   = (const float*)d_in[10];
    float* out        = (float*)d_out;

    const int packTotal = 2 * MOD_STRIDE;
    pack_weights_kernel<<<(packTotal + 255) / 256, 256>>>(W1, W2, W3);

    const int smem_bytes = 2 * ROWS_TILE * LD * (int)sizeof(__half);
    cudaFuncSetAttribute(fused_mlp_kernel,
                         cudaFuncAttributeMaxDynamicSharedMemorySize, smem_bytes);
    fused_mlp_kernel<<<RTOT / ROWS_TILE, NTHREADS, smem_bytes>>>(
        x, ln_g, ln_b, b1, b2, b3, W4, b4, out);
}

// round 16
// speedup vs baseline: 1.2866x; 1.2866x over previous
#include <cuda_runtime.h>
#include <cuda_fp16.h>
#include <math.h>
#include <stdint.h>

// ---------------------------------------------------------------------------
// PredictorLG fused MLP:  LN -> (GEMM+GELU)x3 -> GEMM(->2) -> log_softmax
// R16: fp16 accumulators (2 regs/mma, zero epilogue cvt) unlock 128-row CTA
// with NPASS=1 all layers: layer1 L1-bytes -30%. 512 thr, 1 CTA/SM.
// Desync: two 8-warp halves through L1, four 4-warp quarters after L2.
// ---------------------------------------------------------------------------

#define ROWS_TILE   128
#define NTHREADS    512
#define LD          392           // padded activation row stride (halfs)
#define RTOT        262144
#define ROWS_PER_M  131072

#define S1 (384*384)
#define S2 (384*192)
#define S3 (192*96)
#define MOD_STRIDE (S1+S2+S3)
#define OFF_L2 (S1)
#define OFF_L3 (S1+S2)

__device__ __align__(16) __half g_packedW[2 * MOD_STRIDE];

// half bars: warps 0-7 / 8-15 (256 threads); quarter bars: 4 warps (128 thr)
#define HALF_BAR(h) \
    asm volatile("bar.sync %0, 256;" :: "r"(1 + (h)) : "memory")
#define QUARTER_BAR(q) \
    asm volatile("bar.sync %0, 128;" :: "r"(3 + (q)) : "memory")

// ---------------------------------------------------------------------------
// Weight repack: W[k][n] fp32 -> fp16 B-fragment layout, single-kt granules:
//   dst = base + ((nt*KT + kt)*32 + lane)*4 + reg*2 + i   (8B per lane per kt)
//   lane = (n%8)*4 + ((k%8)>>1);  reg = (k>>3)&1;  i = k&1
// ---------------------------------------------------------------------------
__global__ void pack_weights_kernel(const float* __restrict__ W1,
                                    const float* __restrict__ W2,
                                    const float* __restrict__ W3) {
    int idx = blockIdx.x * blockDim.x + threadIdx.x;
    const float* src;
    int K, N, r, m, layerOff;
    if (idx < 2 * S1) {
        m = idx / S1; r = idx % S1; K = 384; N = 384;
        src = W1 + m * S1; layerOff = 0;
    } else if (idx < 2 * (S1 + S2)) {
        int e = idx - 2 * S1;
        m = e / S2; r = e % S2; K = 384; N = 192;
        src = W2 + m * S2; layerOff = OFF_L2;
    } else if (idx < 2 * (S1 + S2 + S3)) {
        int e = idx - 2 * (S1 + S2);
        m = e / S3; r = e % S3; K = 192; N = 96;
        src = W3 + m * S3; layerOff = OFF_L3;
    } else {
        return;
    }
    int k = r / N, n = r % N;
    int kt  = k >> 4;
    int KT  = K >> 4;
    int nt  = n >> 3;
    int lane = (n & 7) * 4 + ((k & 7) >> 1);
    int reg  = (k >> 3) & 1;
    int i    = k & 1;
    int dst  = m * MOD_STRIDE + layerOff +
               ((nt * KT + kt) * 32 + lane) * 4 + reg * 2 + i;
    g_packedW[dst] = __float2half(src[k * N + n]);
}

// ---------------------------------------------------------------------------
// mma / ldmatrix / gelu helpers
// ---------------------------------------------------------------------------
// fp16-accumulator MMA: C/D are 2 regs = 4 halves
__device__ __forceinline__ void mma16816_f16(unsigned c[2], const unsigned a[4],
                                             const unsigned b0, const unsigned b1) {
    asm volatile(
        "mma.sync.aligned.m16n8k16.row.col.f16.f16.f16.f16 "
        "{%0,%1}, {%2,%3,%4,%5}, {%6,%7}, {%0,%1};\n"
        : "+r"(c[0]), "+r"(c[1])
        : "r"(a[0]), "r"(a[1]), "r"(a[2]), "r"(a[3]), "r"(b0), "r"(b1));
}

__device__ __forceinline__ void ldmatrix_x4(unsigned r[4], uint32_t addr) {
    asm volatile(
        "ldmatrix.sync.aligned.m8n8.x4.shared.b16 {%0,%1,%2,%3}, [%4];\n"
        : "=r"(r[0]), "=r"(r[1]), "=r"(r[2]), "=r"(r[3])
        : "r"(addr));
}

// packed fp16 GELU (tanh approx, HW MUFU.TANH on f16x2)
__device__ __forceinline__ __half2 gelu_h2(__half2 v) {
    const __half2 c0 = __float2half2_rn(0.7978845608f);
    const __half2 c1 = __float2half2_rn(0.044715f);
    const __half2 hf = __float2half2_rn(0.5f);
    __half2 vv = __hmul2(v, v);
    __half2 u  = __hmul2(v, __hfma2(c1, vv, c0));
    unsigned ui = *(unsigned*)&u, ti;
    asm("tanh.approx.f16x2 %0, %1;" : "=r"(ti) : "r"(ui));
    __half2 t  = *(__half2*)&ti;
    __half2 hv = __hmul2(v, hf);
    return __hfma2(hv, t, hv);
}

// ---------------------------------------------------------------------------
// One GEMM layer (single pass): out = gelu(in @ W[K,N] + bias), fp16 acc.
// Warp grid (16/NGW)(m) x NGW(n): warp owns MI*16 rows x CW=N/NGW cols.
// A: MI ldmatrix.x4 per kt. B: single-kt uint2, 2-slot circular prefetch.
// ---------------------------------------------------------------------------
template <int K, int N, int MI, int NGW>
__device__ __forceinline__ void gemm_layer(const __half* inBuf,
                                           __half* outBuf,
                                           const __half* __restrict__ Wp,
                                           const float* __restrict__ bias) {
    constexpr int CW  = N / NGW;
    constexpr int NF  = CW / 8;
    constexpr int KT  = K / 16;

    const int tid  = threadIdx.x;
    const int lane = tid & 31;
    const int wid  = tid >> 5;
    const int wm   = wid / NGW;
    const int wn   = wid % NGW;

    uint32_t sA = (uint32_t)__cvta_generic_to_shared(inBuf);
    const int rbase    = wm * (MI * 16);
    const int arow     = rbase + (lane & 15);
    const int acol_off = (lane >> 4) * 8;
    const uint32_t aBase = sA + (uint32_t)((arow * LD + acol_off) * 2);

    const uint2* bb = (const uint2*)Wp;

    unsigned acc[MI][NF][2];
#pragma unroll
    for (int mi = 0; mi < MI; ++mi)
#pragma unroll
        for (int nf = 0; nf < NF; ++nf) {
            acc[mi][nf][0] = 0u;
            acc[mi][nf][1] = 0u;
        }

    const int colbase = wn * CW;
    const int ntbase  = colbase >> 3;
    const uint2* bwarp = bb + (size_t)ntbase * KT * 32 + lane;
    const int cb = colbase + (lane & 3) * 2;

    // B: 2-slot circular single-kt prefetch (uint2 = 8B/lane)
    uint2 bf[2][NF];
#pragma unroll
    for (int nf = 0; nf < NF; ++nf)
        bf[0][nf] = __ldg(bwarp + (size_t)nf * KT * 32);

#pragma unroll
    for (int kt = 0; kt < KT; ++kt) {
        const int cur = kt & 1;
        if (kt + 1 < KT) {
#pragma unroll
            for (int nf = 0; nf < NF; ++nf)
                bf[cur ^ 1][nf] =
                    __ldg(bwarp + (size_t)nf * KT * 32 + (kt + 1) * 32);
        }

#pragma unroll
        for (int mi = 0; mi < MI; ++mi) {
            unsigned a[4];
            ldmatrix_x4(a, aBase + (uint32_t)((mi * 16 * LD + kt * 16) * 2));
#pragma unroll
            for (int nf = 0; nf < NF; ++nf)
                mma16816_f16(acc[mi][nf], a, bf[cur][nf].x, bf[cur][nf].y);
        }
    }

    // epilogue: half2 bias + packed gelu + store (no cvt — acc already f16x2)
    const int r0 = rbase + (lane >> 2);
#pragma unroll
    for (int nf = 0; nf < NF; ++nf) {
        const int c = cb + nf * 8;
        const __half2 bh = __floats2half2_rn(__ldg(bias + c),
                                             __ldg(bias + c + 1));
#pragma unroll
        for (int mi = 0; mi < MI; ++mi) {
            const int row = r0 + mi * 16;
            __half2 v0 = __hadd2(*(__half2*)&acc[mi][nf][0], bh);
            __half2 v1 = __hadd2(*(__half2*)&acc[mi][nf][1], bh);
            *(__half2*)(outBuf + row * LD + c)       = gelu_h2(v0);
            *(__half2*)(outBuf + (row + 8) * LD + c) = gelu_h2(v1);
        }
    }
}

// ---------------------------------------------------------------------------
// Fused kernel — 128 rows/CTA, 512 threads, 1 CTA/SM.
// ---------------------------------------------------------------------------
__global__ void __launch_bounds__(NTHREADS, 1)
fused_mlp_kernel(const float* __restrict__ x,
                 const float* __restrict__ ln_g,
                 const float* __restrict__ ln_b,
                 const float* __restrict__ b1,
                 const float* __restrict__ b2,
                 const float* __restrict__ b3,
                 const float* __restrict__ W4,
                 const float* __restrict__ b4,
                 float* __restrict__ out) {
    extern __shared__ __align__(16) char smem_raw[];
    __half* bufA = (__half*)smem_raw;                               // [128][392]
    __half* bufB = bufA + ROWS_TILE * LD;                           // [128][392]

    const int tid  = threadIdx.x;
    const int lane = tid & 31;
    const int wid  = tid >> 5;
    const int half = wid >> 3;       // 0..1 (8 warps each, 64 rows)
    const int quar = wid >> 2;       // 0..3 (4 warps each, 32 rows)
    const long row0 = (long)blockIdx.x * ROWS_TILE;
    const int m = (int)(row0 / ROWS_PER_M);

    // ------------------- Stage 0: LayerNorm -> bufA (fp16) -----------------
    {
        float4 g4[3], bb4[3];
#pragma unroll
        for (int j = 0; j < 3; ++j) {
            g4[j]  = ((const float4*)(ln_g + m * 384))[j * 32 + lane];
            bb4[j] = ((const float4*)(ln_b + m * 384))[j * 32 + lane];
        }
        // warp w handles rows w*8 .. w*8+7 (half-local: warps 0-7 = rows 0-63)
#pragma unroll
        for (int t = 0; t < 8; ++t) {
            const int r = wid * 8 + t;
            const float4* xr = (const float4*)(x + (row0 + r) * 384);
            float4 v[3];
            float s = 0.f, q = 0.f;
#pragma unroll
            for (int j = 0; j < 3; ++j) {
                v[j] = xr[j * 32 + lane];
                s += v[j].x + v[j].y + v[j].z + v[j].w;
                q += v[j].x * v[j].x + v[j].y * v[j].y +
                     v[j].z * v[j].z + v[j].w * v[j].w;
            }
#pragma unroll
            for (int off = 16; off; off >>= 1) {
                s += __shfl_xor_sync(0xffffffffu, s, off);
                q += __shfl_xor_sync(0xffffffffu, q, off);
            }
            const float mu   = s * (1.0f / 384.0f);
            const float var  = q * (1.0f / 384.0f) - mu * mu;
            const float rinv = rsqrtf(var + 1e-5f);
#pragma unroll
            for (int j = 0; j < 3; ++j) {
                const int c = (j * 32 + lane) * 4;
                float y0 = (v[j].x - mu) * rinv * g4[j].x + bb4[j].x;
                float y1 = (v[j].y - mu) * rinv * g4[j].y + bb4[j].y;
                float y2 = (v[j].z - mu) * rinv * g4[j].z + bb4[j].z;
                float y3 = (v[j].w - mu) * rinv * g4[j].w + bb4[j].w;
                *(__half2*)(bufA + r * LD + c)     = __floats2half2_rn(y0, y1);
                *(__half2*)(bufA + r * LD + c + 2) = __floats2half2_rn(y2, y3);
            }
        }
    }

    const __half* WpBase = g_packedW + (size_t)m * MOD_STRIDE;

    // ------------------- Layer 1: 384->384  mg=2 (mi=4), ng=8 --------------
    HALF_BAR(half);
    gemm_layer<384, 384, 4, 8>(bufA, bufB, WpBase, b1 + m * 384);

    // ------------------- Layer 2: 384->192  mg=4 (mi=2), ng=4 --------------
    HALF_BAR(half);   // L2 quarter reads rows subset of its half's L1 output
    gemm_layer<384, 192, 2, 4>(bufB, bufA, WpBase + OFF_L2, b2 + m * 192);

    // ------------------- Layer 3: 192->96   mg=4 (mi=2), ng=4 --------------
    QUARTER_BAR(quar);  // L3 quarter reads exactly its own L2 rows
    gemm_layer<192, 96, 2, 4>(bufA, bufB, WpBase + OFF_L3, b3 + m * 96);

    // ------------------- Layer 4: 96 -> 2 + log_softmax (quarter-local) ----
    QUARTER_BAR(quar);
    {
        const int glt  = (wid & 3) * 32 + lane;   // 0..127 within quarter
        const int r    = quar * 32 + (glt >> 2);  // 32 rows per quarter
        const int part = glt & 3;
        const float* w4 = W4 + m * 192;
        const __half* hrow = bufB + r * LD;
        float z0 = 0.f, z1 = 0.f;
#pragma unroll
        for (int kk = 0; kk < 12; ++kk) {
            const int k = part * 24 + kk * 2;
            __half2 hv = *(const __half2*)(hrow + k);
            float a0 = __half2float(hv.x);
            float a1 = __half2float(hv.y);
            z0 += a0 * __ldg(w4 + k * 2)       + a1 * __ldg(w4 + (k + 1) * 2);
            z1 += a0 * __ldg(w4 + k * 2 + 1)   + a1 * __ldg(w4 + (k + 1) * 2 + 1);
        }
        z0 += __shfl_xor_sync(0xffffffffu, z0, 1);
        z0 += __shfl_xor_sync(0xffffffffu, z0, 2);
        z1 += __shfl_xor_sync(0xffffffffu, z1, 1);
        z1 += __shfl_xor_sync(0xffffffffu, z1, 2);
        if (part == 0) {
            z0 += __ldg(b4 + m * 2 + 0);
            z1 += __ldg(b4 + m * 2 + 1);
            const float mx  = fmaxf(z0, z1);
            const float lse = mx + logf(expf(z0 - mx) + expf(z1 - mx));
            float* o = out + (row0 + r) * 2;
            o[0] = z0 - lse;
            o[1] = z1 - lse;
        }
    }
}

// ---------------------------------------------------------------------------
// Launch
// ---------------------------------------------------------------------------
extern "C" void kernel_launch(void* const* d_in, const int* in_sizes, int n_in,
                              void* d_out, int out_size) {
    const float* x    = (const float*)d_in[0];
    const float* ln_g = (const float*)d_in[1];
    const float* ln_b = (const float*)d_in[2];
    const float* W1   = (const float*)d_in[3];
    const float* b1   = (const float*)d_in[4];
    const float* W2   = (const float*)d_in[5];
    const float* b2   = (const float*)d_in[6];
    const float* W3   = (const float*)d_in[7];
    const float* b3   = (const float*)d_in[8];
    const float* W4   = (const float*)d_in[9];
    const float* b4   = (const float*)d_in[10];
    float* out        = (float*)d_out;

    const int packTotal = 2 * MOD_STRIDE;
    pack_weights_kernel<<<(packTotal + 255) / 256, 256>>>(W1, W2, W3);

    const int smem_bytes = 2 * ROWS_TILE * LD * (int)sizeof(__half);
    cudaFuncSetAttribute(fused_mlp_kernel,
                         cudaFuncAttributeMaxDynamicSharedMemorySize, smem_bytes);
    fused_mlp_kernel<<<RTOT / ROWS_TILE, NTHREADS, smem_bytes>>>(
        x, ln_g, ln_b, b1, b2, b3, W4, b4, out);
}

// round 17
// speedup vs baseline: 1.3983x; 1.0868x over previous
#include <cuda_runtime.h>
#include <cuda_fp16.h>
#include <math.h>
#include <stdint.h>

// ---------------------------------------------------------------------------
// PredictorLG fused MLP:  LN -> (GEMM+GELU)x3 -> GEMM(->2) -> log_softmax
// R17: R14 chassis (64 rows, 256 thr, 2 CTAs/SM) + fp16 accumulators +
// layer1 warp grid 1(m)x8(n) single-pass (B bytes halve; -30% L1 on layer1).
// Layers 2/3 keep 2(m)x4(n); L2->L4 group-local barriers; cross-CTA desync.
// ---------------------------------------------------------------------------

#define ROWS_TILE   64
#define NTHREADS    256
#define LD          392           // padded activation row stride (halfs)
#define RTOT        262144
#define ROWS_PER_M  131072

#define S1 (384*384)
#define S2 (384*192)
#define S3 (192*96)
#define MOD_STRIDE (S1+S2+S3)
#define OFF_L2 (S1)
#define OFF_L3 (S1+S2)

__device__ __align__(16) __half g_packedW[2 * MOD_STRIDE];

// group bars: 4 consecutive warps (128 threads), group g = wid>>2
#define GROUP_BAR(g) \
    asm volatile("bar.sync %0, 128;" :: "r"(1 + (g)) : "memory")

// ---------------------------------------------------------------------------
// Weight repack: W[k][n] fp32 -> fp16 B-fragment layout, single-kt granules:
//   dst = base + ((nt*KT + kt)*32 + lane)*4 + reg*2 + i   (8B per lane per kt)
//   lane = (n%8)*4 + ((k%8)>>1);  reg = (k>>3)&1;  i = k&1
// ---------------------------------------------------------------------------
__global__ void pack_weights_kernel(const float* __restrict__ W1,
                                    const float* __restrict__ W2,
                                    const float* __restrict__ W3) {
    int idx = blockIdx.x * blockDim.x + threadIdx.x;
    const float* src;
    int K, N, r, m, layerOff;
    if (idx < 2 * S1) {
        m = idx / S1; r = idx % S1; K = 384; N = 384;
        src = W1 + m * S1; layerOff = 0;
    } else if (idx < 2 * (S1 + S2)) {
        int e = idx - 2 * S1;
        m = e / S2; r = e % S2; K = 384; N = 192;
        src = W2 + m * S2; layerOff = OFF_L2;
    } else if (idx < 2 * (S1 + S2 + S3)) {
        int e = idx - 2 * (S1 + S2);
        m = e / S3; r = e % S3; K = 192; N = 96;
        src = W3 + m * S3; layerOff = OFF_L3;
    } else {
        return;
    }
    int k = r / N, n = r % N;
    int kt  = k >> 4;
    int KT  = K >> 4;
    int nt  = n >> 3;
    int lane = (n & 7) * 4 + ((k & 7) >> 1);
    int reg  = (k >> 3) & 1;
    int i    = k & 1;
    int dst  = m * MOD_STRIDE + layerOff +
               ((nt * KT + kt) * 32 + lane) * 4 + reg * 2 + i;
    g_packedW[dst] = __float2half(src[k * N + n]);
}

// ---------------------------------------------------------------------------
// mma / ldmatrix / gelu helpers
// ---------------------------------------------------------------------------
// fp16-accumulator MMA: C/D are 2 regs = 4 halves
__device__ __forceinline__ void mma16816_f16(unsigned c[2], const unsigned a[4],
                                             const unsigned b0, const unsigned b1) {
    asm volatile(
        "mma.sync.aligned.m16n8k16.row.col.f16.f16.f16.f16 "
        "{%0,%1}, {%2,%3,%4,%5}, {%6,%7}, {%0,%1};\n"
        : "+r"(c[0]), "+r"(c[1])
        : "r"(a[0]), "r"(a[1]), "r"(a[2]), "r"(a[3]), "r"(b0), "r"(b1));
}

__device__ __forceinline__ void ldmatrix_x4(unsigned r[4], uint32_t addr) {
    asm volatile(
        "ldmatrix.sync.aligned.m8n8.x4.shared.b16 {%0,%1,%2,%3}, [%4];\n"
        : "=r"(r[0]), "=r"(r[1]), "=r"(r[2]), "=r"(r[3])
        : "r"(addr));
}

// packed fp16 GELU (tanh approx, HW MUFU.TANH on f16x2)
__device__ __forceinline__ __half2 gelu_h2(__half2 v) {
    const __half2 c0 = __float2half2_rn(0.7978845608f);
    const __half2 c1 = __float2half2_rn(0.044715f);
    const __half2 hf = __float2half2_rn(0.5f);
    __half2 vv = __hmul2(v, v);
    __half2 u  = __hmul2(v, __hfma2(c1, vv, c0));
    unsigned ui = *(unsigned*)&u, ti;
    asm("tanh.approx.f16x2 %0, %1;" : "=r"(ti) : "r"(ui));
    __half2 t  = *(__half2*)&ti;
    __half2 hv = __hmul2(v, hf);
    return __hfma2(hv, t, hv);
}

// ---------------------------------------------------------------------------
// One GEMM layer (single pass): out = gelu(in @ W[K,N] + bias), fp16 acc.
// Warp grid (8/NGW)(m) x NGW(n): warp owns MI*16 rows x CW=N/NGW cols.
// A: MI ldmatrix.x4 per kt. B: single-kt uint2, 2-slot circular prefetch.
// ---------------------------------------------------------------------------
template <int K, int N, int MI, int NGW>
__device__ __forceinline__ void gemm_layer(const __half* inBuf,
                                           __half* outBuf,
                                           const __half* __restrict__ Wp,
                                           const float* __restrict__ bias) {
    constexpr int CW  = N / NGW;
    constexpr int NF  = CW / 8;
    constexpr int KT  = K / 16;

    const int tid  = threadIdx.x;
    const int lane = tid & 31;
    const int wid  = tid >> 5;
    const int wm   = wid / NGW;
    const int wn   = wid % NGW;

    uint32_t sA = (uint32_t)__cvta_generic_to_shared(inBuf);
    const int rbase    = wm * (MI * 16);
    const int arow     = rbase + (lane & 15);
    const int acol_off = (lane >> 4) * 8;
    const uint32_t aBase = sA + (uint32_t)((arow * LD + acol_off) * 2);

    const uint2* bb = (const uint2*)Wp;

    unsigned acc[MI][NF][2];
#pragma unroll
    for (int mi = 0; mi < MI; ++mi)
#pragma unroll
        for (int nf = 0; nf < NF; ++nf) {
            acc[mi][nf][0] = 0u;
            acc[mi][nf][1] = 0u;
        }

    const int colbase = wn * CW;
    const int ntbase  = colbase >> 3;
    const uint2* bwarp = bb + (size_t)ntbase * KT * 32 + lane;
    const int cb = colbase + (lane & 3) * 2;

    // B: 2-slot circular single-kt prefetch (uint2 = 8B/lane)
    uint2 bf[2][NF];
#pragma unroll
    for (int nf = 0; nf < NF; ++nf)
        bf[0][nf] = __ldg(bwarp + (size_t)nf * KT * 32);

#pragma unroll
    for (int kt = 0; kt < KT; ++kt) {
        const int cur = kt & 1;
        if (kt + 1 < KT) {
#pragma unroll
            for (int nf = 0; nf < NF; ++nf)
                bf[cur ^ 1][nf] =
                    __ldg(bwarp + (size_t)nf * KT * 32 + (kt + 1) * 32);
        }

#pragma unroll
        for (int mi = 0; mi < MI; ++mi) {
            unsigned a[4];
            ldmatrix_x4(a, aBase + (uint32_t)((mi * 16 * LD + kt * 16) * 2));
#pragma unroll
            for (int nf = 0; nf < NF; ++nf)
                mma16816_f16(acc[mi][nf], a, bf[cur][nf].x, bf[cur][nf].y);
        }
    }

    // epilogue: half2 bias + packed gelu + store (acc already f16x2)
    const int r0 = rbase + (lane >> 2);
#pragma unroll
    for (int nf = 0; nf < NF; ++nf) {
        const int c = cb + nf * 8;
        const __half2 bh = __floats2half2_rn(__ldg(bias + c),
                                             __ldg(bias + c + 1));
#pragma unroll
        for (int mi = 0; mi < MI; ++mi) {
            const int row = r0 + mi * 16;
            __half2 v0 = __hadd2(*(__half2*)&acc[mi][nf][0], bh);
            __half2 v1 = __hadd2(*(__half2*)&acc[mi][nf][1], bh);
            *(__half2*)(outBuf + row * LD + c)       = gelu_h2(v0);
            *(__half2*)(outBuf + (row + 8) * LD + c) = gelu_h2(v1);
        }
    }
}

// ---------------------------------------------------------------------------
// Fused kernel — 64 rows/CTA, 256 threads, 2 CTAs/SM.
// ---------------------------------------------------------------------------
__global__ void __launch_bounds__(NTHREADS, 2)
fused_mlp_kernel(const float* __restrict__ x,
                 const float* __restrict__ ln_g,
                 const float* __restrict__ ln_b,
                 const float* __restrict__ b1,
                 const float* __restrict__ b2,
                 const float* __restrict__ b3,
                 const float* __restrict__ W4,
                 const float* __restrict__ b4,
                 float* __restrict__ out) {
    extern __shared__ __align__(16) char smem_raw[];
    __half* bufA = (__half*)smem_raw;                               // [64][392]
    __half* bufB = bufA + ROWS_TILE * LD;                           // [64][392]

    const int tid  = threadIdx.x;
    const int lane = tid & 31;
    const int wid  = tid >> 5;
    const int grp  = wid >> 2;       // 0..1, groups of 4 consecutive warps
    const long row0 = (long)blockIdx.x * ROWS_TILE;
    const int m = (int)(row0 / ROWS_PER_M);

    // ------------------- Stage 0: LayerNorm -> bufA (fp16) -----------------
    {
        float4 g4[3], bb4[3];
#pragma unroll
        for (int j = 0; j < 3; ++j) {
            g4[j]  = ((const float4*)(ln_g + m * 384))[j * 32 + lane];
            bb4[j] = ((const float4*)(ln_b + m * 384))[j * 32 + lane];
        }
#pragma unroll
        for (int t = 0; t < 8; ++t) {
            const int r = wid * 8 + t;
            const float4* xr = (const float4*)(x + (row0 + r) * 384);
            float4 v[3];
            float s = 0.f, q = 0.f;
#pragma unroll
            for (int j = 0; j < 3; ++j) {
                v[j] = xr[j * 32 + lane];
                s += v[j].x + v[j].y + v[j].z + v[j].w;
                q += v[j].x * v[j].x + v[j].y * v[j].y +
                     v[j].z * v[j].z + v[j].w * v[j].w;
            }
#pragma unroll
            for (int off = 16; off; off >>= 1) {
                s += __shfl_xor_sync(0xffffffffu, s, off);
                q += __shfl_xor_sync(0xffffffffu, q, off);
            }
            const float mu   = s * (1.0f / 384.0f);
            const float var  = q * (1.0f / 384.0f) - mu * mu;
            const float rinv = rsqrtf(var + 1e-5f);
#pragma unroll
            for (int j = 0; j < 3; ++j) {
                const int c = (j * 32 + lane) * 4;
                float y0 = (v[j].x - mu) * rinv * g4[j].x + bb4[j].x;
                float y1 = (v[j].y - mu) * rinv * g4[j].y + bb4[j].y;
                float y2 = (v[j].z - mu) * rinv * g4[j].z + bb4[j].z;
                float y3 = (v[j].w - mu) * rinv * g4[j].w + bb4[j].w;
                *(__half2*)(bufA + r * LD + c)     = __floats2half2_rn(y0, y1);
                *(__half2*)(bufA + r * LD + c + 2) = __floats2half2_rn(y2, y3);
            }
        }
    }

    const __half* WpBase = g_packedW + (size_t)m * MOD_STRIDE;

    // ------------------- Layer 1: 384->384, 1(m)x8(n), single pass ---------
    __syncthreads();              // L1 reads all rows (mg=1)
    gemm_layer<384, 384, 4, 8>(bufA, bufB, WpBase, b1 + m * 384);

    // ------------------- Layer 2: 384->192, 2(m)x4(n) ----------------------
    __syncthreads();              // L2 group reads cols written by all warps
    gemm_layer<384, 192, 2, 4>(bufB, bufA, WpBase + OFF_L2, b2 + m * 192);

    // ------------------- Layer 3: 192->96, 2(m)x4(n), group-local ----------
    GROUP_BAR(grp);               // L3 group reads exactly its own L2 rows
    gemm_layer<192, 96, 2, 4>(bufA, bufB, WpBase + OFF_L3, b3 + m * 96);

    // ------------------- Layer 4: 96 -> 2 + log_softmax (group-local) ------
    GROUP_BAR(grp);
    {
        const int glt  = (wid & 3) * 32 + lane;   // 0..127 within group
        const int r    = grp * 32 + (glt >> 2);   // 32 rows per group
        const int part = glt & 3;
        const float* w4 = W4 + m * 192;
        const __half* hrow = bufB + r * LD;
        float z0 = 0.f, z1 = 0.f;
#pragma unroll
        for (int kk = 0; kk < 12; ++kk) {
            const int k = part * 24 + kk * 2;
            __half2 hv = *(const __half2*)(hrow + k);
            float a0 = __half2float(hv.x);
            float a1 = __half2float(hv.y);
            z0 += a0 * __ldg(w4 + k * 2)       + a1 * __ldg(w4 + (k + 1) * 2);
            z1 += a0 * __ldg(w4 + k * 2 + 1)   + a1 * __ldg(w4 + (k + 1) * 2 + 1);
        }
        z0 += __shfl_xor_sync(0xffffffffu, z0, 1);
        z0 += __shfl_xor_sync(0xffffffffu, z0, 2);
        z1 += __shfl_xor_sync(0xffffffffu, z1, 1);
        z1 += __shfl_xor_sync(0xffffffffu, z1, 2);
        if (part == 0) {
            z0 += __ldg(b4 + m * 2 + 0);
            z1 += __ldg(b4 + m * 2 + 1);
            const float mx  = fmaxf(z0, z1);
            const float lse = mx + logf(expf(z0 - mx) + expf(z1 - mx));
            float* o = out + (row0 + r) * 2;
            o[0] = z0 - lse;
            o[1] = z1 - lse;
        }
    }
}

// ---------------------------------------------------------------------------
// Launch
// ---------------------------------------------------------------------------
extern "C" void kernel_launch(void* const* d_in, const int* in_sizes, int n_in,
                              void* d_out, int out_size) {
    const float* x    = (const float*)d_in[0];
    const float* ln_g = (const float*)d_in[1];
    const float* ln_b = (const float*)d_in[2];
    const float* W1   = (const float*)d_in[3];
    const float* b1   = (const float*)d_in[4];
    const float* W2   = (const float*)d_in[5];
    const float* b2   = (const float*)d_in[6];
    const float* W3   = (const float*)d_in[7];
    const float* b3   = (const float*)d_in[8];
    const float* W4   = (const float*)d_in[9];
    const float* b4   = (const float*)d_in[10];
    float* out        = (float*)d_out;

    const int packTotal = 2 * MOD_STRIDE;
    pack_weights_kernel<<<(packTotal + 255) / 256, 256>>>(W1, W2, W3);

    const int smem_bytes = 2 * ROWS_TILE * LD * (int)sizeof(__half);
    cudaFuncSetAttribute(fused_mlp_kernel,
                         cudaFuncAttributeMaxDynamicSharedMemorySize, smem_bytes);
    fused_mlp_kernel<<<RTOT / ROWS_TILE, NTHREADS, smem_bytes>>>(
        x, ln_g, ln_b, b1, b2, b3, W4, b4, out);
}